// round 10
// baseline (speedup 1.0000x reference)
#include <cuda_runtime.h>
#include <cuda_fp16.h>
#include <cstdint>

#define B_SZ    8192
#define DK      128
#define EPSV    1e-6f
#define CEPS    (128.0f * 1e-6f * 1e-6f)
#define MARGINF 0.2f
#define NCTA    148
#define NCHUNK  2048          // 32 row-blocks (256 rows) x 64 col-chunks (128 cols)

// SMEM: A tile 256 rows x 272B (256 + 16 pad), B buffers 128 rows x 272B + meta.
// Row start word = 68r mod 32 = 4r mod 32 -> conflict-free ldmatrix (proven R7/R9).
#define RS      272
#define SM_A    0
#define A_BYTES (256 * RS)                 // 69632
#define SM_B0   A_BYTES
#define OFF_N2  (128 * RS)                 // within a B buffer: after data
#define OFF_TG  (128 * RS + 512)
#define BUFSZ   (128 * RS + 640)           // 35456
#define SM_B1   (SM_B0 + BUFSZ)
#define SMEM_TOTAL (SM_B1 + BUFSZ)         // 140544

__device__ __align__(16) __half   g_e1h[B_SZ * DK];
__device__ __align__(16) __half   g_e2h[B_SZ * DK];
__device__ __align__(16) float    g_n1[B_SZ];
__device__ __align__(16) float    g_n2[B_SZ];
__device__ __align__(16) unsigned g_posmax[B_SZ];   // float bits; >=0 so uint order == float order
__device__ __align__(16) unsigned g_negmin[B_SZ];
__device__ __align__(16) char     g_tgt[B_SZ];
__device__ int g_is32;
__device__ int g_done;

__device__ __forceinline__ uint32_t smem_u32(const void* p) {
    uint32_t a;
    asm("{ .reg .u64 t; cvta.to.shared.u64 t, %1; cvt.u32.u64 %0, t; }" : "=r"(a) : "l"(p));
    return a;
}

#define CPA16(d, s)  asm volatile("cp.async.cg.shared.global [%0], [%1], 16;" :: "r"(d), "l"(s))
#define CPCOMMIT()   asm volatile("cp.async.commit_group;" ::: "memory")
#define CPWAIT(n)    asm volatile("cp.async.wait_group %0;" :: "n"(n) : "memory")

#define LDSM4(r, addr)                                                          \
    asm volatile("ldmatrix.sync.aligned.m8n8.x4.shared.b16 {%0,%1,%2,%3}, [%4];" \
        : "=r"((r)[0]), "=r"((r)[1]), "=r"((r)[2]), "=r"((r)[3]) : "r"(addr))

#define MMA(C, A, B0v, B1v)                                                     \
    asm volatile(                                                               \
        "mma.sync.aligned.m16n8k16.row.col.f32.f16.f16.f32 "                    \
        "{%0,%1,%2,%3}, {%4,%5,%6,%7}, {%8,%9}, {%0,%1,%2,%3};"                 \
        : "+f"((C)[0]), "+f"((C)[1]), "+f"((C)[2]), "+f"((C)[3])                \
        : "r"((A)[0]), "r"((A)[1]), "r"((A)[2]), "r"((A)[3]),                   \
          "r"(B0v), "r"(B1v))

// ---------------------------------------------------------------------------
// Kernel 0: target dtype detect (512 odd words; P(wrong)=2^-512) + reset g_done.
// ---------------------------------------------------------------------------
__global__ void detect_kernel(const unsigned* __restrict__ w) {
    __shared__ unsigned sred[16];
    unsigned acc = w[2 * threadIdx.x + 1];
#pragma unroll
    for (int o = 16; o; o >>= 1) acc |= __shfl_xor_sync(0xFFFFFFFFu, acc, o);
    if ((threadIdx.x & 31) == 0) sred[threadIdx.x >> 5] = acc;
    __syncthreads();
    if (threadIdx.x == 0) {
        acc = 0;
#pragma unroll
        for (int i = 0; i < 16; i++) acc |= sred[i];
        g_is32 = (acc != 0);
        g_done = 0;
    }
}

// ---------------------------------------------------------------------------
// Kernel 1: fp32 -> fp16 convert + row norms + init + tgt decode. One warp/row.
// ---------------------------------------------------------------------------
__global__ void split_kernel(const float* __restrict__ e1, const float* __restrict__ e2,
                             const unsigned* __restrict__ tw) {
    int w   = threadIdx.x >> 5;
    int lid = threadIdx.x & 31;
    int r   = blockIdx.x * 8 + w;

    float4 a = ((const float4*)(e1 + (size_t)r * DK))[lid];
    float4 b = ((const float4*)(e2 + (size_t)r * DK))[lid];

    __half2 a0 = __floats2half2_rn(a.x, a.y), a1 = __floats2half2_rn(a.z, a.w);
    __half2 b0 = __floats2half2_rn(b.x, b.y), b1 = __floats2half2_rn(b.z, b.w);
    ((uint2*)(g_e1h + (size_t)r * DK))[lid] = make_uint2(*(uint32_t*)&a0, *(uint32_t*)&a1);
    ((uint2*)(g_e2h + (size_t)r * DK))[lid] = make_uint2(*(uint32_t*)&b0, *(uint32_t*)&b1);

    float s1 = a.x + a.y + a.z + a.w;
    float q1 = a.x * a.x + a.y * a.y + a.z * a.z + a.w * a.w;
    float s2 = b.x + b.y + b.z + b.w;
    float q2 = b.x * b.x + b.y * b.y + b.z * b.z + b.w * b.w;
#pragma unroll
    for (int o = 16; o; o >>= 1) {
        s1 += __shfl_xor_sync(0xFFFFFFFFu, s1, o);
        q1 += __shfl_xor_sync(0xFFFFFFFFu, q1, o);
        s2 += __shfl_xor_sync(0xFFFFFFFFu, s2, o);
        q2 += __shfl_xor_sync(0xFFFFFFFFu, q2, o);
    }
    if (lid == 0) {
        g_n1[r] = q1 + 2.0f * EPSV * s1;
        g_n2[r] = q2 - 2.0f * EPSV * s2;
        g_posmax[r] = 0u;
        g_negmin[r] = 0x7f800000u;
        g_tgt[r] = (char)(g_is32 ? tw[r] : tw[2 * r]);
    }
}

// ---------------------------------------------------------------------------
// B-chunk loader: 128 columns (fp16 rows of e2) + n2/tgt metadata. 512 threads.
// ---------------------------------------------------------------------------
__device__ __forceinline__ void load_b(uint32_t bb, int j, int tid) {
    int cb   = j * 128;
    int row  = tid >> 2;
    int part = (tid & 3) * 64;
    const char* src = (const char*)(g_e2h + (size_t)(cb + row) * DK) + part;
    uint32_t dst = bb + (uint32_t)row * RS + part;
#pragma unroll
    for (int i = 0; i < 4; i++) CPA16(dst + i * 16, src + i * 16);
    if (tid < 32) {
        CPA16(bb + OFF_N2 + tid * 16, (const char*)(g_n2 + cb) + tid * 16);
    } else if (tid < 40) {
        CPA16(bb + OFF_TG + (tid - 32) * 16, (const char*)(g_tgt + cb) + (tid - 32) * 16);
    }
}

// ---------------------------------------------------------------------------
// Kernel 2: persistent fp16 GEMM + fused masked row max/min + fused final.
// 148 CTAs x 512 threads. Work = 2048 chunks (256 rows x 128 cols), static
// contiguous ranges (row-block-major -> <=2 A reloads per CTA).
// 16 warps: wr=w&3 (64-row group), wc=w>>2 (32-col group). Warp tile 64x32.
// ---------------------------------------------------------------------------
__global__ void __launch_bounds__(512, 1) mma_kernel(float* __restrict__ out) {
    extern __shared__ char smem[];
    __shared__ int s_last;
    __shared__ float s_red[32];
    uint32_t sb = smem_u32(smem);
    int tid  = threadIdx.x;
    int w    = tid >> 5;
    int lane = tid & 31;
    int tq   = lane >> 2;
    int tr   = lane & 3;
    int wr   = w & 3;
    int wc   = w >> 2;
    int bid  = blockIdx.x;

    int c0 = (NCHUNK * bid) / NCTA;
    int c1 = (NCHUNK * (bid + 1)) / NCTA;

    uint32_t abase = sb + (uint32_t)(wr * 64 + (lane & 15)) * RS + ((lane >> 4) << 4);

    while (c0 < c1) {
        int rb     = c0 >> 6;
        int segEnd = min(c1, (rb + 1) << 6);
        int j0     = c0 & 63;
        int jn     = segEnd - c0;

        // stage A tile (256 rows x 256B)
        {
            int row = tid >> 1;
            int h   = (tid & 1) * 128;
            const char* src = (const char*)(g_e1h + (size_t)(rb * 256 + row) * DK) + h;
            uint32_t dst = sb + (uint32_t)row * RS + h;
#pragma unroll
            for (int i = 0; i < 8; i++) CPA16(dst + i * 16, src + i * 16);
        }
        CPCOMMIT();
        load_b(sb + SM_B0, j0, tid);
        CPCOMMIT();
        if (jn > 1) { load_b(sb + SM_B1, j0 + 1, tid); CPCOMMIT(); }

        float maxp[8], minn[8];
#pragma unroll
        for (int s = 0; s < 8; s++) {
            maxp[s] = __int_as_float(0xff800000);
            minn[s] = __int_as_float(0x7f800000);
        }

        for (int q = 0; q < jn; q++) {
            uint32_t bb = sb + ((q & 1) ? SM_B1 : SM_B0);
            if (q + 1 < jn) { CPWAIT(1); } else { CPWAIT(0); }
            __syncthreads();

            float c[4][4][4];
#pragma unroll
            for (int mt = 0; mt < 4; mt++)
#pragma unroll
                for (int nt = 0; nt < 4; nt++)
#pragma unroll
                    for (int i = 0; i < 4; i++) c[mt][nt][i] = 0.0f;

            uint32_t bbase = bb + (uint32_t)(wc * 32 + (lane & 15)) * RS + ((lane >> 4) << 4);
#pragma unroll
            for (int ks = 0; ks < 8; ks++) {
                uint32_t ah[4][4], bh[2][4];
#pragma unroll
                for (int mt = 0; mt < 4; mt++) LDSM4(ah[mt], abase + mt * (16 * RS) + ks * 32);
#pragma unroll
                for (int p = 0; p < 2; p++)    LDSM4(bh[p], bbase + p * (16 * RS) + ks * 32);
#pragma unroll
                for (int mt = 0; mt < 4; mt++)
#pragma unroll
                    for (int p = 0; p < 2; p++) {
                        MMA(c[mt][2 * p],     ah[mt], bh[p][0], bh[p][2]);
                        MMA(c[mt][2 * p + 1], ah[mt], bh[p][1], bh[p][3]);
                    }
            }

            // fold chunk: t = n2 - 2*dot per row-slot
            const float* n2b = (const float*)(smem + ((q & 1) ? SM_B1 : SM_B0) + OFF_N2);
            const char*  tgb = (const char*)(smem + ((q & 1) ? SM_B1 : SM_B0) + OFF_TG);
#pragma unroll
            for (int nt = 0; nt < 4; nt++)
#pragma unroll
                for (int b = 0; b < 2; b++) {
                    int jl = wc * 32 + nt * 8 + tr * 2 + b;
                    float n2v = n2b[jl];
                    char  tv  = tgb[jl];
#pragma unroll
                    for (int mt = 0; mt < 4; mt++)
#pragma unroll
                        for (int hx = 0; hx < 2; hx++) {
                            float t = fmaf(-2.0f, c[mt][nt][hx * 2 + b], n2v);
                            int s = mt * 2 + hx;
                            if (tv) maxp[s] = fmaxf(maxp[s], t);
                            else    minn[s] = fminf(minn[s], t);
                        }
                }

            __syncthreads();
            if (q + 2 < jn) { load_b(bb, j0 + q + 2, tid); CPCOMMIT(); }
        }

        // flush segment: quad-reduce, apply n1 + CEPS + clamp, atomics
#pragma unroll
        for (int s = 0; s < 8; s++) {
#pragma unroll
            for (int o = 1; o <= 2; o <<= 1) {
                maxp[s] = fmaxf(maxp[s], __shfl_xor_sync(0xFFFFFFFFu, maxp[s], o));
                minn[s] = fminf(minn[s], __shfl_xor_sync(0xFFFFFFFFu, minn[s], o));
            }
            if (tr == 0) {
                int grow = rb * 256 + wr * 64 + (s >> 1) * 16 + tq + (s & 1) * 8;
                float n1v = g_n1[grow];
                float pm = fmaxf(n1v + maxp[s] + CEPS, 0.0f);   // -inf -> 0 (vs init 0, harmless)
                float nm = fmaxf(n1v + minn[s] + CEPS, 0.0f);   // +inf stays +inf
                atomicMax(&g_posmax[grow], __float_as_uint(pm));
                atomicMin(&g_negmin[grow], __float_as_uint(nm));
            }
        }
        c0 = segEnd;
    }

    // fused final reduction: last CTA to finish computes the scalar loss
    __syncthreads();
    if (tid == 0) {
        __threadfence();
        s_last = (atomicAdd(&g_done, 1) == NCTA - 1);
    }
    __syncthreads();
    if (s_last) {
        float s = 0.0f, cnt = 0.0f;
#pragma unroll 4
        for (int i = tid; i < B_SZ; i += 512) {
            if (__ldcg(&g_tgt[i])) {
                float pm = __uint_as_float(__ldcg(&g_posmax[i]));
                float nm = __uint_as_float(__ldcg(&g_negmin[i]));
                float v  = sqrtf(pm) - sqrtf(nm) + MARGINF;   // nm==inf -> -inf -> clamped
                s   += fmaxf(v, 0.0f);
                cnt += 1.0f;
            }
        }
#pragma unroll
        for (int o = 16; o; o >>= 1) {
            s   += __shfl_xor_sync(0xFFFFFFFFu, s, o);
            cnt += __shfl_xor_sync(0xFFFFFFFFu, cnt, o);
        }
        if (lane == 0) { s_red[w] = s; s_red[16 + w] = cnt; }
        __syncthreads();
        if (tid == 0) {
            s = 0.0f; cnt = 0.0f;
#pragma unroll
            for (int i = 0; i < 16; i++) { s += s_red[i]; cnt += s_red[16 + i]; }
            out[0] = s / cnt;
        }
    }
}

extern "C" void kernel_launch(void* const* d_in, const int* in_sizes, int n_in,
                              void* d_out, int out_size) {
    const float*    e1 = (const float*)d_in[0];
    const float*    e2 = (const float*)d_in[1];
    const unsigned* tw = (const unsigned*)d_in[2];
    float* out = (float*)d_out;

    cudaFuncSetAttribute(mma_kernel, cudaFuncAttributeMaxDynamicSharedMemorySize, SMEM_TOTAL);

    detect_kernel<<<1, 512>>>(tw);
    split_kernel<<<B_SZ / 8, 256>>>(e1, e2, tw);
    mma_kernel<<<NCTA, 512, SMEM_TOTAL>>>(out);
}

// round 11
// speedup vs baseline: 1.1846x; 1.1846x over previous
#include <cuda_runtime.h>
#include <cuda_fp16.h>
#include <cstdint>

#define B_SZ    8192
#define DK      128
#define EPSV    1e-6f
#define CEPS    (128.0f * 1e-6f * 1e-6f)
#define MARGINF 0.2f
#define NCTA    148
#define NCHUNK  4096          // 64 row-blocks (128 rows) x 64 col-chunks (128 cols)

// fp16 tiles: 128 rows x 128 halfs, row stride 272 B (256 + 16 pad)
// -> row start word = 68r mod 32 = 4r mod 32: conflict-free ldmatrix (proven R7/R9).
#define RSTRIDE 272
#define TILE_B  (128 * RSTRIDE)            // 34816
#define SM_A    0
#define SM_B0   TILE_B
#define OFF_N2  TILE_B                     // within a B buffer: after data
#define OFF_TG  (TILE_B + 512)
#define BUFSZ   (TILE_B + 640)             // 35456
#define SM_B1   (SM_B0 + BUFSZ)
#define SMEM_TOTAL (SM_B1 + BUFSZ)         // 105728

__device__ __align__(16) __half   g_e1h[B_SZ * DK];
__device__ __align__(16) __half   g_e2h[B_SZ * DK];
__device__ __align__(16) float    g_n1[B_SZ];
__device__ __align__(16) float    g_n2[B_SZ];
__device__ __align__(16) unsigned g_posmax[B_SZ];   // float bits; >=0 so uint order == float order
__device__ __align__(16) unsigned g_negmin[B_SZ];
__device__ __align__(16) char     g_tgt32[B_SZ];    // decode assuming int32 target
__device__ __align__(16) char     g_tgt64[B_SZ];    // decode assuming int64 target
__device__ int g_odd;     // OR of odd words; nonzero -> target is int32 (idempotent across replays)
__device__ int g_done;

__device__ __forceinline__ uint32_t smem_u32(const void* p) {
    uint32_t a;
    asm("{ .reg .u64 t; cvta.to.shared.u64 t, %1; cvt.u32.u64 %0, t; }" : "=r"(a) : "l"(p));
    return a;
}

#define CPA16(d, s)  asm volatile("cp.async.cg.shared.global [%0], [%1], 16;" :: "r"(d), "l"(s))
#define CPCOMMIT()   asm volatile("cp.async.commit_group;" ::: "memory")
#define CPWAIT(n)    asm volatile("cp.async.wait_group %0;" :: "n"(n) : "memory")

#define LDSM4(r, addr)                                                          \
    asm volatile("ldmatrix.sync.aligned.m8n8.x4.shared.b16 {%0,%1,%2,%3}, [%4];" \
        : "=r"((r)[0]), "=r"((r)[1]), "=r"((r)[2]), "=r"((r)[3]) : "r"(addr))

#define MMA(C, A, B0v, B1v)                                                     \
    asm volatile(                                                               \
        "mma.sync.aligned.m16n8k16.row.col.f32.f16.f16.f32 "                    \
        "{%0,%1,%2,%3}, {%4,%5,%6,%7}, {%8,%9}, {%0,%1,%2,%3};"                 \
        : "+f"((C)[0]), "+f"((C)[1]), "+f"((C)[2]), "+f"((C)[3])                \
        : "r"((A)[0]), "r"((A)[1]), "r"((A)[2]), "r"((A)[3]),                   \
          "r"(B0v), "r"(B1v))

// ---------------------------------------------------------------------------
// Kernel 1: fp32 -> fp16 convert + row norms + init + both-dtype tgt decode
// + odd-word OR (dtype probe). One warp per row.
// ---------------------------------------------------------------------------
__global__ void split_kernel(const float* __restrict__ e1, const float* __restrict__ e2,
                             const unsigned* __restrict__ tw) {
    int w   = threadIdx.x >> 5;
    int lid = threadIdx.x & 31;
    int r   = blockIdx.x * 8 + w;

    if (blockIdx.x == 0 && threadIdx.x == 0) g_done = 0;

    float4 a = ((const float4*)(e1 + (size_t)r * DK))[lid];
    float4 b = ((const float4*)(e2 + (size_t)r * DK))[lid];

    __half2 a0 = __floats2half2_rn(a.x, a.y), a1 = __floats2half2_rn(a.z, a.w);
    __half2 b0 = __floats2half2_rn(b.x, b.y), b1 = __floats2half2_rn(b.z, b.w);
    ((uint2*)(g_e1h + (size_t)r * DK))[lid] = make_uint2(*(uint32_t*)&a0, *(uint32_t*)&a1);
    ((uint2*)(g_e2h + (size_t)r * DK))[lid] = make_uint2(*(uint32_t*)&b0, *(uint32_t*)&b1);

    float s1 = a.x + a.y + a.z + a.w;
    float q1 = a.x * a.x + a.y * a.y + a.z * a.z + a.w * a.w;
    float s2 = b.x + b.y + b.z + b.w;
    float q2 = b.x * b.x + b.y * b.y + b.z * b.z + b.w * b.w;
#pragma unroll
    for (int o = 16; o; o >>= 1) {
        s1 += __shfl_xor_sync(0xFFFFFFFFu, s1, o);
        q1 += __shfl_xor_sync(0xFFFFFFFFu, q1, o);
        s2 += __shfl_xor_sync(0xFFFFFFFFu, s2, o);
        q2 += __shfl_xor_sync(0xFFFFFFFFu, q2, o);
    }
    if (lid == 0) {
        g_n1[r] = q1 + 2.0f * EPSV * s1;
        g_n2[r] = q2 - 2.0f * EPSV * s2;
        g_posmax[r] = 0u;
        g_negmin[r] = 0x7f800000u;
        g_tgt32[r] = (char)tw[r];
        g_tgt64[r] = (char)tw[2 * r];
        unsigned o = tw[2 * r + 1];          // odd word: nonzero only if int32 layout
        if (o) atomicOr(&g_odd, 1);          // idempotent -> replay-stable
    }
}

// ---------------------------------------------------------------------------
// B-chunk loader: 128 columns (fp16 rows of e2) + n2/tgt metadata. 256 threads.
// ---------------------------------------------------------------------------
__device__ __forceinline__ void load_b(uint32_t bb, int j, int tid, const char* tgt) {
    int cb   = j * 128;
    int row  = tid >> 1;
    int h128 = (tid & 1) * 128;
    const char* src = (const char*)(g_e2h + (size_t)(cb + row) * DK) + h128;
    uint32_t dst = bb + (uint32_t)row * RSTRIDE + h128;
#pragma unroll
    for (int i = 0; i < 8; i++) CPA16(dst + i * 16, src + i * 16);
    if (tid < 32) {
        CPA16(bb + OFF_N2 + tid * 16, (const char*)(g_n2 + cb) + tid * 16);
    } else if (tid < 40) {
        CPA16(bb + OFF_TG + (tid - 32) * 16, tgt + cb + (tid - 32) * 16);
    }
}

// ---------------------------------------------------------------------------
// Kernel 2: persistent single-pass fp16 GEMM + fused masked row max/min +
// fused final scalar. 148 CTAs x 256 threads over 4096 chunks (128x128),
// row-block-major static contiguous ranges (<=2 A reloads per CTA).
// 8 warps: wm=w&3 (rows wm*32..+32), wn=w>>2 (cols wn*64..+64).  [R9 body]
// ---------------------------------------------------------------------------
__global__ void __launch_bounds__(256, 1) mma_kernel(float* __restrict__ out) {
    extern __shared__ char smem[];
    __shared__ int s_last;
    __shared__ float s_red[16];
    uint32_t sb = smem_u32(smem);
    int tid  = threadIdx.x;
    int w    = tid >> 5;
    int lane = tid & 31;
    int tq   = lane >> 2;
    int tr   = lane & 3;
    int wm   = w & 3;
    int wn   = w >> 2;
    int bid  = blockIdx.x;

    const char* tgt = (*(volatile int*)&g_odd) ? g_tgt32 : g_tgt64;

    int c0 = (NCHUNK * bid) / NCTA;
    int c1 = (NCHUNK * (bid + 1)) / NCTA;

    while (c0 < c1) {
        int rb     = c0 >> 6;
        int segEnd = min(c1, (rb + 1) << 6);
        int j0     = c0 & 63;
        int jn     = segEnd - c0;
        int r0     = rb * 128;

        // stage A tile
        {
            int row  = tid >> 1;
            int h128 = (tid & 1) * 128;
            const char* src = (const char*)(g_e1h + (size_t)(r0 + row) * DK) + h128;
            uint32_t dst = sb + SM_A + (uint32_t)row * RSTRIDE + h128;
#pragma unroll
            for (int i = 0; i < 8; i++) CPA16(dst + i * 16, src + i * 16);
        }
        CPCOMMIT();
        load_b(sb + SM_B0, j0, tid, tgt);
        CPCOMMIT();
        if (jn > 1) {
            load_b(sb + SM_B1, j0 + 1, tid, tgt);
            CPCOMMIT();
            CPWAIT(2);        // A staged
        } else {
            CPWAIT(1);        // A staged
        }
        __syncthreads();

        // A fragments -> registers (2 mt x 8 ksteps x 4 regs)
        uint32_t ahr[2][8][4];
        {
            uint32_t abase = sb + SM_A + (uint32_t)(wm * 32 + (lane & 15)) * RSTRIDE
                           + ((lane >> 4) << 4);
#pragma unroll
            for (int mt = 0; mt < 2; mt++)
#pragma unroll
                for (int ks = 0; ks < 8; ks++)
                    LDSM4(ahr[mt][ks], abase + mt * 16 * RSTRIDE + ks * 32);
        }

        float maxp[4], minn[4];
#pragma unroll
        for (int s = 0; s < 4; s++) {
            maxp[s] = __int_as_float(0xff800000);   // -inf
            minn[s] = __int_as_float(0x7f800000);   // +inf
        }

        for (int q = 0; q < jn; q++) {
            uint32_t bb = sb + ((q & 1) ? SM_B1 : SM_B0);
            if (q + 1 < jn) { CPWAIT(1); } else { CPWAIT(0); }
            __syncthreads();

            float c[2][8][4];
#pragma unroll
            for (int mt = 0; mt < 2; mt++)
#pragma unroll
                for (int nt = 0; nt < 8; nt++)
#pragma unroll
                    for (int i = 0; i < 4; i++) c[mt][nt][i] = 0.0f;

            uint32_t bbase = bb + (uint32_t)(wn * 64 + (lane & 15)) * RSTRIDE
                           + ((lane >> 4) << 4);
#pragma unroll
            for (int ks = 0; ks < 8; ks++) {
                uint32_t bh[4][4];
#pragma unroll
                for (int p = 0; p < 4; p++) LDSM4(bh[p], bbase + p * 16 * RSTRIDE + ks * 32);
#pragma unroll
                for (int mt = 0; mt < 2; mt++)
#pragma unroll
                    for (int p = 0; p < 4; p++) {
                        MMA(c[mt][2 * p],     ahr[mt][ks], bh[p][0], bh[p][2]);
                        MMA(c[mt][2 * p + 1], ahr[mt][ks], bh[p][1], bh[p][3]);
                    }
            }

            // fold chunk: t = n2 - 2*dot; track max over positives / min over negatives
            const float* n2b = (const float*)(smem + ((q & 1) ? SM_B1 : SM_B0) + OFF_N2);
            const char*  tgb = (const char*)(smem + ((q & 1) ? SM_B1 : SM_B0) + OFF_TG);
#pragma unroll
            for (int nt = 0; nt < 8; nt++)
#pragma unroll
                for (int b = 0; b < 2; b++) {
                    int jl = wn * 64 + nt * 8 + tr * 2 + b;
                    float n2v = n2b[jl];
                    char  tv  = tgb[jl];
#pragma unroll
                    for (int mt = 0; mt < 2; mt++)
#pragma unroll
                        for (int hx = 0; hx < 2; hx++) {
                            float t = fmaf(-2.0f, c[mt][nt][hx * 2 + b], n2v);
                            int s = mt * 2 + hx;
                            if (tv) maxp[s] = fmaxf(maxp[s], t);
                            else    minn[s] = fminf(minn[s], t);
                        }
                }

            __syncthreads();      // all warps done with this buffer
            if (q + 2 < jn) {
                load_b(bb, j0 + q + 2, tid, tgt);
                CPCOMMIT();
            }
        }

        // flush segment: quad-reduce, apply n1 + CEPS + clamp, one atomic/row-slot
#pragma unroll
        for (int s = 0; s < 4; s++) {
#pragma unroll
            for (int o = 1; o <= 2; o <<= 1) {
                maxp[s] = fmaxf(maxp[s], __shfl_xor_sync(0xFFFFFFFFu, maxp[s], o));
                minn[s] = fminf(minn[s], __shfl_xor_sync(0xFFFFFFFFu, minn[s], o));
            }
            if (tr == 0) {
                int grow = r0 + wm * 32 + (s >> 1) * 16 + tq + (s & 1) * 8;
                float n1v = g_n1[grow];
                float pm = fmaxf(n1v + maxp[s] + CEPS, 0.0f);   // -inf -> 0 (vs init 0, harmless)
                float nm = fmaxf(n1v + minn[s] + CEPS, 0.0f);   // +inf stays +inf
                atomicMax(&g_posmax[grow], __float_as_uint(pm));
                atomicMin(&g_negmin[grow], __float_as_uint(nm));
            }
        }
        c0 = segEnd;
    }

    // fused final reduction: last CTA to finish computes the scalar loss
    __syncthreads();
    if (tid == 0) {
        __threadfence();
        s_last = (atomicAdd(&g_done, 1) == NCTA - 1);
    }
    __syncthreads();
    if (s_last) {
        float s = 0.0f, cnt = 0.0f;
#pragma unroll 8
        for (int i = tid; i < B_SZ; i += 256) {
            if (__ldcg((const char*)tgt + i)) {
                float pm = __uint_as_float(__ldcg(&g_posmax[i]));
                float nm = __uint_as_float(__ldcg(&g_negmin[i]));
                float v  = sqrtf(pm) - sqrtf(nm) + MARGINF;   // nm==inf -> -inf -> clamped
                s   += fmaxf(v, 0.0f);
                cnt += 1.0f;
            }
        }
#pragma unroll
        for (int o = 16; o; o >>= 1) {
            s   += __shfl_xor_sync(0xFFFFFFFFu, s, o);
            cnt += __shfl_xor_sync(0xFFFFFFFFu, cnt, o);
        }
        if (lane == 0) { s_red[w] = s; s_red[8 + w] = cnt; }
        __syncthreads();
        if (tid == 0) {
            s = 0.0f; cnt = 0.0f;
#pragma unroll
            for (int i = 0; i < 8; i++) { s += s_red[i]; cnt += s_red[8 + i]; }
            out[0] = s / cnt;
        }
    }
}

extern "C" void kernel_launch(void* const* d_in, const int* in_sizes, int n_in,
                              void* d_out, int out_size) {
    const float*    e1 = (const float*)d_in[0];
    const float*    e2 = (const float*)d_in[1];
    const unsigned* tw = (const unsigned*)d_in[2];
    float* out = (float*)d_out;

    cudaFuncSetAttribute(mma_kernel, cudaFuncAttributeMaxDynamicSharedMemorySize, SMEM_TOTAL);

    split_kernel<<<B_SZ / 8, 256>>>(e1, e2, tw);
    mma_kernel<<<NCTA, 256, SMEM_TOTAL>>>(out);
}

// round 16
// speedup vs baseline: 1.1923x; 1.0065x over previous
#include <cuda_runtime.h>
#include <cuda_fp16.h>
#include <cstdint>

#define B_SZ    8192
#define DK      128
#define EPSV    1e-6f
#define CEPS    (128.0f * 1e-6f * 1e-6f)
#define MARGINF 0.2f
#define NCTA    148
#define NCHUNK  4096          // 64 row-blocks (128 rows) x 64 col-chunks (128 cols)

// fp16 tiles: 128 rows x 128 halfs, row stride 272 B (256 + 16 pad)
// -> row start word = 68r mod 32 = 4r mod 32: conflict-free ldmatrix (proven R7/R9).
#define RSTRIDE 272
#define TILE_B  (128 * RSTRIDE)            // 34816
#define SM_A    0
#define SM_B0   TILE_B
#define OFF_N2  TILE_B                     // within a B buffer: after data
#define OFF_TG  (TILE_B + 512)
#define BUFSZ   (TILE_B + 640)             // 35456
#define SM_B1   (SM_B0 + BUFSZ)
#define SMEM_TOTAL (SM_B1 + BUFSZ)         // 105728

__device__ __align__(16) __half   g_e1h[B_SZ * DK];
__device__ __align__(16) __half   g_e2h[B_SZ * DK];
__device__ __align__(16) float    g_n1[B_SZ];
__device__ __align__(16) float    g_n2[B_SZ];
__device__ __align__(16) unsigned g_posmax[B_SZ];   // float bits; >=0 so uint order == float order
__device__ __align__(16) unsigned g_negmin[B_SZ];
__device__ __align__(16) char     g_tgt32[B_SZ];    // decode assuming int32 target
__device__ __align__(16) char     g_tgt64[B_SZ];    // decode assuming int64 target
__device__ int g_odd;     // OR of odd words; nonzero -> target is int32 (idempotent across replays)
__device__ int g_done;

__device__ __forceinline__ uint32_t smem_u32(const void* p) {
    uint32_t a;
    asm("{ .reg .u64 t; cvta.to.shared.u64 t, %1; cvt.u32.u64 %0, t; }" : "=r"(a) : "l"(p));
    return a;
}

#define CPA16(d, s)  asm volatile("cp.async.cg.shared.global [%0], [%1], 16;" :: "r"(d), "l"(s))
#define CPCOMMIT()   asm volatile("cp.async.commit_group;" ::: "memory")
#define CPWAIT(n)    asm volatile("cp.async.wait_group %0;" :: "n"(n) : "memory")

#define LDSM4(r, addr)                                                          \
    asm volatile("ldmatrix.sync.aligned.m8n8.x4.shared.b16 {%0,%1,%2,%3}, [%4];" \
        : "=r"((r)[0]), "=r"((r)[1]), "=r"((r)[2]), "=r"((r)[3]) : "r"(addr))

#define MMA(C, A, B0v, B1v)                                                     \
    asm volatile(                                                               \
        "mma.sync.aligned.m16n8k16.row.col.f32.f16.f16.f32 "                    \
        "{%0,%1,%2,%3}, {%4,%5,%6,%7}, {%8,%9}, {%0,%1,%2,%3};"                 \
        : "+f"((C)[0]), "+f"((C)[1]), "+f"((C)[2]), "+f"((C)[3])                \
        : "r"((A)[0]), "r"((A)[1]), "r"((A)[2]), "r"((A)[3]),                   \
          "r"(B0v), "r"(B1v))

// ---------------------------------------------------------------------------
// Kernel 1: fp32 -> fp16 convert + row norms + init + both-dtype tgt decode
// + odd-word OR (dtype probe). One warp per row.
// ---------------------------------------------------------------------------
__global__ void split_kernel(const float* __restrict__ e1, const float* __restrict__ e2,
                             const unsigned* __restrict__ tw) {
    int w   = threadIdx.x >> 5;
    int lid = threadIdx.x & 31;
    int r   = blockIdx.x * 8 + w;

    if (blockIdx.x == 0 && threadIdx.x == 0) g_done = 0;

    float4 a = ((const float4*)(e1 + (size_t)r * DK))[lid];
    float4 b = ((const float4*)(e2 + (size_t)r * DK))[lid];

    __half2 a0 = __floats2half2_rn(a.x, a.y), a1 = __floats2half2_rn(a.z, a.w);
    __half2 b0 = __floats2half2_rn(b.x, b.y), b1 = __floats2half2_rn(b.z, b.w);
    ((uint2*)(g_e1h + (size_t)r * DK))[lid] = make_uint2(*(uint32_t*)&a0, *(uint32_t*)&a1);
    ((uint2*)(g_e2h + (size_t)r * DK))[lid] = make_uint2(*(uint32_t*)&b0, *(uint32_t*)&b1);

    float s1 = a.x + a.y + a.z + a.w;
    float q1 = a.x * a.x + a.y * a.y + a.z * a.z + a.w * a.w;
    float s2 = b.x + b.y + b.z + b.w;
    float q2 = b.x * b.x + b.y * b.y + b.z * b.z + b.w * b.w;
#pragma unroll
    for (int o = 16; o; o >>= 1) {
        s1 += __shfl_xor_sync(0xFFFFFFFFu, s1, o);
        q1 += __shfl_xor_sync(0xFFFFFFFFu, q1, o);
        s2 += __shfl_xor_sync(0xFFFFFFFFu, s2, o);
        q2 += __shfl_xor_sync(0xFFFFFFFFu, q2, o);
    }
    if (lid == 0) {
        g_n1[r] = q1 + 2.0f * EPSV * s1;
        g_n2[r] = q2 - 2.0f * EPSV * s2;
        g_posmax[r] = 0u;
        g_negmin[r] = 0x7f800000u;
        g_tgt32[r] = (char)tw[r];
        g_tgt64[r] = (char)tw[2 * r];
        unsigned o = tw[2 * r + 1];          // odd word: nonzero only if int32 layout
        if (o) atomicOr(&g_odd, 1);          // idempotent -> replay-stable
    }
}

// ---------------------------------------------------------------------------
// B-chunk loader: 128 columns (fp16 rows of e2) + n2/tgt metadata. 256 threads.
// ---------------------------------------------------------------------------
__device__ __forceinline__ void load_b(uint32_t bb, int j, int tid, const char* tgt) {
    int cb   = j * 128;
    int row  = tid >> 1;
    int h128 = (tid & 1) * 128;
    const char* src = (const char*)(g_e2h + (size_t)(cb + row) * DK) + h128;
    uint32_t dst = bb + (uint32_t)row * RSTRIDE + h128;
#pragma unroll
    for (int i = 0; i < 8; i++) CPA16(dst + i * 16, src + i * 16);
    if (tid < 32) {
        CPA16(bb + OFF_N2 + tid * 16, (const char*)(g_n2 + cb) + tid * 16);
    } else if (tid < 40) {
        CPA16(bb + OFF_TG + (tid - 32) * 16, tgt + cb + (tid - 32) * 16);
    }
}

// ---------------------------------------------------------------------------
// Kernel 2: persistent single-pass fp16 GEMM + fused masked row max/min +
// fused final scalar. 148 CTAs x 256 threads over 4096 chunks (128x128),
// row-block-major static contiguous ranges (R11 config, known-good).
// 8 warps: wm=w&3 (rows wm*32..+32), wn=w>>2 (cols wn*64..+64).
// A fragments register-resident; B fragments software-pipelined in registers
// (LDSM of ks+1 issued before MMAs of ks) to break the LDSM->MMA stall.
// ---------------------------------------------------------------------------
__global__ void __launch_bounds__(256, 1) mma_kernel(float* __restrict__ out) {
    extern __shared__ char smem[];
    __shared__ int s_last;
    __shared__ float s_red[16];
    uint32_t sb = smem_u32(smem);
    int tid  = threadIdx.x;
    int w    = tid >> 5;
    int lane = tid & 31;
    int tq   = lane >> 2;
    int tr   = lane & 3;
    int wm   = w & 3;
    int wn   = w >> 2;
    int bid  = blockIdx.x;

    const char* tgt = (*(volatile int*)&g_odd) ? g_tgt32 : g_tgt64;

    int c0 = (NCHUNK * bid) / NCTA;
    int c1 = (NCHUNK * (bid + 1)) / NCTA;

    while (c0 < c1) {
        int rb     = c0 >> 6;
        int segEnd = min(c1, (rb + 1) << 6);
        int j0     = c0 & 63;
        int jn     = segEnd - c0;
        int r0     = rb * 128;

        // stage A tile
        {
            int row  = tid >> 1;
            int h128 = (tid & 1) * 128;
            const char* src = (const char*)(g_e1h + (size_t)(r0 + row) * DK) + h128;
            uint32_t dst = sb + SM_A + (uint32_t)row * RSTRIDE + h128;
#pragma unroll
            for (int i = 0; i < 8; i++) CPA16(dst + i * 16, src + i * 16);
        }
        CPCOMMIT();
        load_b(sb + SM_B0, j0, tid, tgt);
        CPCOMMIT();
        if (jn > 1) {
            load_b(sb + SM_B1, j0 + 1, tid, tgt);
            CPCOMMIT();
            CPWAIT(2);        // A staged
        } else {
            CPWAIT(1);        // A staged
        }
        __syncthreads();

        // A fragments -> registers (2 mt x 8 ksteps x 4 regs)
        uint32_t ahr[2][8][4];
        {
            uint32_t abase = sb + SM_A + (uint32_t)(wm * 32 + (lane & 15)) * RSTRIDE
                           + ((lane >> 4) << 4);
#pragma unroll
            for (int mt = 0; mt < 2; mt++)
#pragma unroll
                for (int ks = 0; ks < 8; ks++)
                    LDSM4(ahr[mt][ks], abase + mt * 16 * RSTRIDE + ks * 32);
        }

        float maxp[4], minn[4];
#pragma unroll
        for (int s = 0; s < 4; s++) {
            maxp[s] = __int_as_float(0xff800000);   // -inf
            minn[s] = __int_as_float(0x7f800000);   // +inf
        }

        for (int q = 0; q < jn; q++) {
            uint32_t bb = sb + ((q & 1) ? SM_B1 : SM_B0);
            if (q + 1 < jn) { CPWAIT(1); } else { CPWAIT(0); }
            __syncthreads();

            float c[2][8][4];
#pragma unroll
            for (int mt = 0; mt < 2; mt++)
#pragma unroll
                for (int nt = 0; nt < 8; nt++)
#pragma unroll
                    for (int i = 0; i < 4; i++) c[mt][nt][i] = 0.0f;

            uint32_t bbase = bb + (uint32_t)(wn * 64 + (lane & 15)) * RSTRIDE
                           + ((lane >> 4) << 4);

            // software-pipelined B fragments: LDSM(ks+1) issued before MMAs(ks)
            uint32_t bhbuf[2][4][4];
#pragma unroll
            for (int p = 0; p < 4; p++) LDSM4(bhbuf[0][p], bbase + p * 16 * RSTRIDE);
#pragma unroll
            for (int ks = 0; ks < 8; ks++) {
                int cur = ks & 1;
                if (ks < 7) {
#pragma unroll
                    for (int p = 0; p < 4; p++)
                        LDSM4(bhbuf[cur ^ 1][p], bbase + p * 16 * RSTRIDE + (ks + 1) * 32);
                }
#pragma unroll
                for (int mt = 0; mt < 2; mt++)
#pragma unroll
                    for (int p = 0; p < 4; p++) {
                        MMA(c[mt][2 * p],     ahr[mt][ks], bhbuf[cur][p][0], bhbuf[cur][p][2]);
                        MMA(c[mt][2 * p + 1], ahr[mt][ks], bhbuf[cur][p][1], bhbuf[cur][p][3]);
                    }
            }

            // fold chunk: t = n2 - 2*dot; track max over positives / min over negatives
            const float* n2b = (const float*)(smem + ((q & 1) ? SM_B1 : SM_B0) + OFF_N2);
            const char*  tgb = (const char*)(smem + ((q & 1) ? SM_B1 : SM_B0) + OFF_TG);
#pragma unroll
            for (int nt = 0; nt < 8; nt++)
#pragma unroll
                for (int b = 0; b < 2; b++) {
                    int jl = wn * 64 + nt * 8 + tr * 2 + b;
                    float n2v = n2b[jl];
                    char  tv  = tgb[jl];
#pragma unroll
                    for (int mt = 0; mt < 2; mt++)
#pragma unroll
                        for (int hx = 0; hx < 2; hx++) {
                            float t = fmaf(-2.0f, c[mt][nt][hx * 2 + b], n2v);
                            int s = mt * 2 + hx;
                            if (tv) maxp[s] = fmaxf(maxp[s], t);
                            else    minn[s] = fminf(minn[s], t);
                        }
                }

            __syncthreads();      // all warps done with this buffer
            if (q + 2 < jn) {
                load_b(bb, j0 + q + 2, tid, tgt);
                CPCOMMIT();
            }
        }

        // flush segment: quad-reduce, apply n1 + CEPS + clamp, one atomic/row-slot
#pragma unroll
        for (int s = 0; s < 4; s++) {
#pragma unroll
            for (int o = 1; o <= 2; o <<= 1) {
                maxp[s] = fmaxf(maxp[s], __shfl_xor_sync(0xFFFFFFFFu, maxp[s], o));
                minn[s] = fminf(minn[s], __shfl_xor_sync(0xFFFFFFFFu, minn[s], o));
            }
            if (tr == 0) {
                int grow = r0 + wm * 32 + (s >> 1) * 16 + tq + (s & 1) * 8;
                float n1v = g_n1[grow];
                float pm = fmaxf(n1v + maxp[s] + CEPS, 0.0f);   // -inf -> 0 (vs init 0, harmless)
                float nm = fmaxf(n1v + minn[s] + CEPS, 0.0f);   // +inf stays +inf
                atomicMax(&g_posmax[grow], __float_as_uint(pm));
                atomicMin(&g_negmin[grow], __float_as_uint(nm));
            }
        }
        c0 = segEnd;
    }

    // fused final reduction: last CTA to finish computes the scalar loss
    __syncthreads();
    if (tid == 0) {
        __threadfence();
        s_last = (atomicAdd(&g_done, 1) == NCTA - 1);
    }
    __syncthreads();
    if (s_last) {
        float s = 0.0f, cnt = 0.0f;
#pragma unroll 8
        for (int i = tid; i < B_SZ; i += 256) {
            if (__ldcg((const char*)tgt + i)) {
                float pm = __uint_as_float(__ldcg(&g_posmax[i]));
                float nm = __uint_as_float(__ldcg(&g_negmin[i]));
                float v  = sqrtf(pm) - sqrtf(nm) + MARGINF;   // nm==inf -> -inf -> clamped
                s   += fmaxf(v, 0.0f);
                cnt += 1.0f;
            }
        }
#pragma unroll
        for (int o = 16; o; o >>= 1) {
            s   += __shfl_xor_sync(0xFFFFFFFFu, s, o);
            cnt += __shfl_xor_sync(0xFFFFFFFFu, cnt, o);
        }
        if (lane == 0) { s_red[w] = s; s_red[8 + w] = cnt; }
        __syncthreads();
        if (tid == 0) {
            s = 0.0f; cnt = 0.0f;
#pragma unroll
            for (int i = 0; i < 8; i++) { s += s_red[i]; cnt += s_red[8 + i]; }
            out[0] = s / cnt;
        }
    }
}

extern "C" void kernel_launch(void* const* d_in, const int* in_sizes, int n_in,
                              void* d_out, int out_size) {
    const float*    e1 = (const float*)d_in[0];
    const float*    e2 = (const float*)d_in[1];
    const unsigned* tw = (const unsigned*)d_in[2];
    float* out = (float*)d_out;

    cudaFuncSetAttribute(mma_kernel, cudaFuncAttributeMaxDynamicSharedMemorySize, SMEM_TOTAL);

    split_kernel<<<B_SZ / 8, 256>>>(e1, e2, tw);
    mma_kernel<<<NCTA, 256, SMEM_TOTAL>>>(out);
}